// round 6
// baseline (speedup 1.0000x reference)
#include <cuda_runtime.h>
#include <cuda_bf16.h>

#define N_NODES  500000
#define N_EDGES  2500000
#define N_GRAPHS 1024
#define NPT      4      // nodes per thread in fused pool kernel
#define SCAN_B   1024   // elements per scan block
#define N_SCANB  ((N_NODES + SCAN_B - 1) / SCAN_B)   // 489

// ---------------- scratch (device globals: no allocation allowed) ----------
__device__ int   g_rowcnt[N_NODES];              // histogram, then fill cursor
__device__ int   g_rowstart[N_NODES + 1];        // CSR row offsets (in-edges by dst)
__device__ int   g_srcs[N_EDGES];                // CSR column idx: src per in-edge
__device__ int   g_bsum[512];                    // scan block partials
__device__ int   g_boff[512];                    // scan block offsets (exclusive)
__device__ __align__(16) float g_h1[(size_t)N_NODES * 16];    // relu(conv1)
__device__ __align__(16) float g_sums[(size_t)N_GRAPHS * 32]; // per-graph sums
__device__ float g_cnt[N_GRAPHS];

__device__ __forceinline__ void red4(float* p, float a, float b, float c, float d) {
    asm volatile("red.global.add.v4.f32 [%0], {%1, %2, %3, %4};"
                 :: "l"(p), "f"(a), "f"(b), "f"(c), "f"(d) : "memory");
}
__device__ __forceinline__ void red1(float* p, float a) {
    asm volatile("red.global.add.f32 [%0], %1;" :: "l"(p), "f"(a) : "memory");
}

// ---------------- 1: zero histogram + pool buffers -------------------------
__global__ void k_zero() {
    int i = blockIdx.x * blockDim.x + threadIdx.x;
    if (i < N_GRAPHS) {
        g_cnt[i] = 0.0f;
        float4* s = (float4*)(g_sums + (size_t)i * 32);
#pragma unroll
        for (int q = 0; q < 8; q++) s[q] = make_float4(0.f, 0.f, 0.f, 0.f);
    }
    if (i < N_NODES) g_rowcnt[i] = 0;
}

// ---------------- 2: in-degree histogram -----------------------------------
__global__ void k_hist(const int* __restrict__ ei) {
    int e = blockIdx.x * blockDim.x + threadIdx.x;
    if (e >= N_EDGES) return;
    atomicAdd(&g_rowcnt[ei[N_EDGES + e]], 1);   // no return value -> RED
}

// ---------------- 3a: per-block inclusive scan -> exclusive within block ---
__global__ void k_scan1() {
    __shared__ int sh[SCAN_B];
    int gid = blockIdx.x * SCAN_B + threadIdx.x;
    int v = (gid < N_NODES) ? g_rowcnt[gid] : 0;
    sh[threadIdx.x] = v;
    __syncthreads();
#pragma unroll
    for (int off = 1; off < SCAN_B; off <<= 1) {
        int t = (threadIdx.x >= off) ? sh[threadIdx.x - off] : 0;
        __syncthreads();
        sh[threadIdx.x] += t;
        __syncthreads();
    }
    if (gid < N_NODES) g_rowstart[gid] = sh[threadIdx.x] - v;  // exclusive
    if (threadIdx.x == SCAN_B - 1) g_bsum[blockIdx.x] = sh[SCAN_B - 1];
}

// ---------------- 3b: scan the block partials (single block) ---------------
__global__ void k_scan2() {
    __shared__ int sh[512];
    int v = (threadIdx.x < N_SCANB) ? g_bsum[threadIdx.x] : 0;
    sh[threadIdx.x] = v;
    __syncthreads();
#pragma unroll
    for (int off = 1; off < 512; off <<= 1) {
        int t = (threadIdx.x >= off) ? sh[threadIdx.x - off] : 0;
        __syncthreads();
        sh[threadIdx.x] += t;
        __syncthreads();
    }
    g_boff[threadIdx.x] = sh[threadIdx.x] - v;  // exclusive
}

// ---------------- 3c: add block offsets, re-zero cursors -------------------
__global__ void k_scan3() {
    int i = blockIdx.x * blockDim.x + threadIdx.x;
    if (i >= N_NODES) return;
    g_rowstart[i] += g_boff[i / SCAN_B];
    g_rowcnt[i] = 0;
    if (i == 0) g_rowstart[N_NODES] = N_EDGES;
}

// ---------------- 4: fill CSR column array ---------------------------------
__global__ void k_fill(const int* __restrict__ ei) {
    int e = blockIdx.x * blockDim.x + threadIdx.x;
    if (e >= N_EDGES) return;
    int s = ei[e];
    int d = ei[N_EDGES + e];
    int pos = g_rowstart[d] + atomicAdd(&g_rowcnt[d], 1);
    g_srcs[pos] = s;
}

// ---------------- 5: gather-aggregate x, linear1+relu -> h1 ----------------
__global__ void k_agg1(const float2* __restrict__ x,
                       const float* __restrict__ W1, const float* __restrict__ b1) {
    __shared__ float sW[48];   // W1 (2x16) then b1 (16)
    if (threadIdx.x < 32)      sW[threadIdx.x] = W1[threadIdx.x];
    else if (threadIdx.x < 48) sW[threadIdx.x] = b1[threadIdx.x - 32];
    __syncthreads();
    int i = blockIdx.x * blockDim.x + threadIdx.x;
    if (i >= N_NODES) return;
    int s0 = g_rowstart[i], s1 = g_rowstart[i + 1];
    float2 xi = __ldg(&x[i]);                 // self loop
    float ax = xi.x, ay = xi.y;
    for (int j = s0; j < s1; j++) {
        float2 xs = __ldg(&x[g_srcs[j]]);
        ax += xs.x; ay += xs.y;
    }
    float deg = (float)(s1 - s0 + 1);
    float4* ph = (float4*)(g_h1 + (size_t)i * 16);
#pragma unroll
    for (int q = 0; q < 4; q++) {
        float4 v;
        v.x = fmaxf(fmaf(ax, sW[4*q+0], fmaf(ay, sW[16+4*q+0], deg * sW[32+4*q+0])), 0.0f);
        v.y = fmaxf(fmaf(ax, sW[4*q+1], fmaf(ay, sW[16+4*q+1], deg * sW[32+4*q+1])), 0.0f);
        v.z = fmaxf(fmaf(ax, sW[4*q+2], fmaf(ay, sW[16+4*q+2], deg * sW[32+4*q+2])), 0.0f);
        v.w = fmaxf(fmaf(ax, sW[4*q+3], fmaf(ay, sW[16+4*q+3], deg * sW[32+4*q+3])), 0.0f);
        ph[q] = v;
    }
}

// ---------------- 6: fused gather-agg2 + linear2 + relu + mean-pool --------
__device__ __forceinline__ void flush_graph(int g, const float* acc, float cc) {
    float* ps = g_sums + (size_t)g * 32;
#pragma unroll
    for (int q = 0; q < 8; q++)
        red4(ps + 4*q, acc[4*q], acc[4*q+1], acc[4*q+2], acc[4*q+3]);
    red1(&g_cnt[g], cc);
}

__global__ void __launch_bounds__(256) k_pool(const int* __restrict__ batch,
                       const float* __restrict__ W2, const float* __restrict__ b2) {
    __shared__ float sW[512 + 32];  // W2 (16x32) then b2 (32)
    for (int t = threadIdx.x; t < 544; t += blockDim.x)
        sW[t] = (t < 512) ? W2[t] : b2[t - 512];
    __syncthreads();

    int t = blockIdx.x * blockDim.x + threadIdx.x;
    int base = t * NPT;
    if (base >= N_NODES) return;
    int end = min(base + NPT, N_NODES);

    float acc[32];
    float cc = 0.0f;
    int curg = -1;

#pragma unroll 1
    for (int i = base; i < end; i++) {
        int g = __ldg(&batch[i]);
        int s0 = g_rowstart[i], s1 = g_rowstart[i + 1];
        float deg = (float)(s1 - s0 + 1);

        // aggregate h1 over in-edges + self
        float4 a0, a1, a2, a3;
        {
            const float4* pr = (const float4*)(g_h1 + (size_t)i * 16);
            a0 = pr[0]; a1 = pr[1]; a2 = pr[2]; a3 = pr[3];
        }
#pragma unroll 1
        for (int j = s0; j < s1; j++) {
            const float4* pr = (const float4*)(g_h1 + (size_t)g_srcs[j] * 16);
            float4 v0 = __ldg(pr + 0), v1 = __ldg(pr + 1);
            float4 v2 = __ldg(pr + 2), v3 = __ldg(pr + 3);
            a0.x += v0.x; a0.y += v0.y; a0.z += v0.z; a0.w += v0.w;
            a1.x += v1.x; a1.y += v1.y; a1.z += v1.z; a1.w += v1.w;
            a2.x += v2.x; a2.y += v2.y; a2.z += v2.z; a2.w += v2.w;
            a3.x += v3.x; a3.y += v3.y; a3.z += v3.z; a3.w += v3.w;
        }
        float hv[16];
        hv[0]=a0.x; hv[1]=a0.y; hv[2]=a0.z; hv[3]=a0.w;
        hv[4]=a1.x; hv[5]=a1.y; hv[6]=a1.z; hv[7]=a1.w;
        hv[8]=a2.x; hv[9]=a2.y; hv[10]=a2.z; hv[11]=a2.w;
        hv[12]=a3.x; hv[13]=a3.y; hv[14]=a3.z; hv[15]=a3.w;

        float out[32];
#pragma unroll
        for (int k = 0; k < 32; k++) out[k] = deg * sW[512 + k];
#pragma unroll
        for (int j = 0; j < 16; j++) {
            float hj = hv[j];
            const float4* wrow = (const float4*)(sW + j * 32);
#pragma unroll
            for (int q = 0; q < 8; q++) {
                float4 w = wrow[q];
                out[4*q+0] = fmaf(hj, w.x, out[4*q+0]);
                out[4*q+1] = fmaf(hj, w.y, out[4*q+1]);
                out[4*q+2] = fmaf(hj, w.z, out[4*q+2]);
                out[4*q+3] = fmaf(hj, w.w, out[4*q+3]);
            }
        }
#pragma unroll
        for (int k = 0; k < 32; k++) out[k] = fmaxf(out[k], 0.0f);

        if (g != curg) {
            if (curg >= 0) flush_graph(curg, acc, cc);
#pragma unroll
            for (int k = 0; k < 32; k++) acc[k] = out[k];
            cc = 1.0f;
            curg = g;
        } else {
#pragma unroll
            for (int k = 0; k < 32; k++) acc[k] += out[k];
            cc += 1.0f;
        }
    }
    if (curg >= 0) flush_graph(curg, acc, cc);
}

// ---------------- 7: final MLP over 1024 graphs ----------------------------
__global__ void k_final(const float* __restrict__ Wf1, const float* __restrict__ bf1,
                        const float* __restrict__ Wf2, const float* __restrict__ bf2,
                        float* __restrict__ out) {
    int g = blockIdx.x * blockDim.x + threadIdx.x;
    if (g >= N_GRAPHS) return;
    float inv = 1.0f / fmaxf(g_cnt[g], 1.0f);
    float p[32];
#pragma unroll
    for (int k = 0; k < 32; k++) p[k] = g_sums[(size_t)g * 32 + k] * inv;

    float o = __ldg(&bf2[0]);
#pragma unroll
    for (int j = 0; j < 16; j++) {
        float s = __ldg(&bf1[j]);
#pragma unroll
        for (int k = 0; k < 32; k++)
            s = fmaf(p[k], __ldg(&Wf1[k * 16 + j]), s);
        o = fmaf(fmaxf(s, 0.0f), __ldg(&Wf2[j]), o);
    }
    out[g] = o;
}

// ---------------- launch ---------------------------------------------------
extern "C" void kernel_launch(void* const* d_in, const int* in_sizes, int n_in,
                              void* d_out, int out_size) {
    const float2* x     = (const float2*)d_in[0];
    const int*    ei    = (const int*)   d_in[1];
    const int*    batch = (const int*)   d_in[2];
    const float*  W1    = (const float*) d_in[3];
    const float*  b1    = (const float*) d_in[4];
    const float*  W2    = (const float*) d_in[5];
    const float*  b2    = (const float*) d_in[6];
    const float*  Wf1   = (const float*) d_in[7];
    const float*  bf1   = (const float*) d_in[8];
    const float*  Wf2   = (const float*) d_in[9];
    const float*  bf2   = (const float*) d_in[10];
    float* out = (float*)d_out;

    const int TB = 256;
    const int NB_NODE = (N_NODES + TB - 1) / TB;
    const int NB_EDGE = (N_EDGES + TB - 1) / TB;

    k_zero <<<NB_NODE, TB>>>();
    k_hist <<<NB_EDGE, TB>>>(ei);
    k_scan1<<<N_SCANB, SCAN_B>>>();
    k_scan2<<<1, 512>>>();
    k_scan3<<<NB_NODE, TB>>>();
    k_fill <<<NB_EDGE, TB>>>(ei);
    k_agg1 <<<NB_NODE, TB>>>(x, W1, b1);
    int pool_threads = (N_NODES + NPT - 1) / NPT;
    k_pool <<<(pool_threads + TB - 1) / TB, TB>>>(batch, W2, b2);
    k_final<<<(N_GRAPHS + TB - 1) / TB, TB>>>(Wf1, bf1, Wf2, bf2, out);
}

// round 8
// speedup vs baseline: 1.1711x; 1.1711x over previous
#include <cuda_runtime.h>
#include <cuda_bf16.h>
#include <cuda_fp16.h>

#define N_NODES  500000
#define N_EDGES  2500000
#define N_GRAPHS 1024
#define NPT      4   // nodes per thread in the pool kernel

// ---------------- scratch (device globals: no allocation allowed) ----------
__device__ __align__(16) float   g_aggx[(size_t)N_NODES * 4];   // {sum_x, sum_y, deg, pad}
__device__ __align__(16) __half2 g_h1h[(size_t)N_NODES * 8];    // relu(conv1) in fp16 (16 feats)
__device__ __align__(16) float   g_aggh[(size_t)N_NODES * 16];  // f32 aggregation of h1
__device__ float g_deg[N_NODES];                                // compact degree
__device__ __align__(16) float g_sums[(size_t)N_GRAPHS * 32];   // per-graph feature sums
__device__ float g_cnt[N_GRAPHS];                               // per-graph node counts

// ---------------- vectorized global reductions -----------------------------
__device__ __forceinline__ void red4(float* p, float a, float b, float c, float d) {
    asm volatile("red.global.add.v4.f32 [%0], {%1, %2, %3, %4};"
                 :: "l"(p), "f"(a), "f"(b), "f"(c), "f"(d) : "memory");
}
__device__ __forceinline__ void red1(float* p, float a) {
    asm volatile("red.global.add.f32 [%0], %1;" :: "l"(p), "f"(a) : "memory");
}

// ---------------- kernel 1: init self-loop contributions + zero pool bufs --
__global__ void k_init(const float2* __restrict__ x) {
    int i = blockIdx.x * blockDim.x + threadIdx.x;
    if (i < N_GRAPHS) {
        g_cnt[i] = 0.0f;
        float4* s = (float4*)(g_sums + (size_t)i * 32);
#pragma unroll
        for (int q = 0; q < 8; q++) s[q] = make_float4(0.f, 0.f, 0.f, 0.f);
    }
    if (i >= N_NODES) return;
    float2 xi = __ldg(&x[i]);
    ((float4*)g_aggx)[i] = make_float4(xi.x, xi.y, 1.0f, 0.0f);  // self loop, deg=1
}

// ---------------- kernel 2: layer-1 edge scatter (pre-linear) --------------
__global__ void k_edge1(const float2* __restrict__ x, const int* __restrict__ ei) {
    int e = blockIdx.x * blockDim.x + threadIdx.x;
    if (e >= N_EDGES) return;
    int s = __ldg(&ei[e]);
    int d = __ldg(&ei[N_EDGES + e]);
    float2 xs = __ldg(&x[s]);
    red4(g_aggx + (size_t)d * 4, xs.x, xs.y, 1.0f, 0.0f);
}

// ---------------- kernel 3: h1 = relu(W1^T*aggx + deg*b1) -> f16 + f32 seed
__global__ void k_node1(const float* __restrict__ W1, const float* __restrict__ b1) {
    __shared__ float sW[48];   // W1 (2x16) then b1 (16)
    if (threadIdx.x < 32)      sW[threadIdx.x] = W1[threadIdx.x];
    else if (threadIdx.x < 48) sW[threadIdx.x] = b1[threadIdx.x - 32];
    __syncthreads();
    int i = blockIdx.x * blockDim.x + threadIdx.x;
    if (i >= N_NODES) return;
    float4 a = ((const float4*)g_aggx)[i];
    float h[16];
#pragma unroll
    for (int j = 0; j < 16; j++)
        h[j] = fmaxf(fmaf(a.x, sW[j], fmaf(a.y, sW[16 + j], a.z * sW[32 + j])), 0.0f);

    // f16 copy for edge gather (2 x 16B stores)
    __half2 hp[8];
#pragma unroll
    for (int q = 0; q < 8; q++) hp[q] = __floats2half2_rn(h[2*q], h[2*q+1]);
    float4* pdst = (float4*)(g_h1h + (size_t)i * 8);
    pdst[0] = ((float4*)hp)[0];
    pdst[1] = ((float4*)hp)[1];

    // exact f32 self-loop seed for the aggregation buffer
    float4* pa = (float4*)(g_aggh + (size_t)i * 16);
#pragma unroll
    for (int q = 0; q < 4; q++)
        pa[q] = make_float4(h[4*q], h[4*q+1], h[4*q+2], h[4*q+3]);

    g_deg[i] = a.z;   // compact degree for the pool kernel
}

// ---------------- kernel 4: layer-2 edge scatter (f16 gather, f32 atomics) -
__global__ void k_edge2(const int* __restrict__ ei) {
    int e = blockIdx.x * blockDim.x + threadIdx.x;
    if (e >= N_EDGES) return;
    int s = __ldg(&ei[e]);
    int d = __ldg(&ei[N_EDGES + e]);
    const float4* hp = (const float4*)(g_h1h + (size_t)s * 8);
    float4 r0 = __ldg(hp + 0);
    float4 r1 = __ldg(hp + 1);
    const __half2* q0 = (const __half2*)&r0;
    const __half2* q1 = (const __half2*)&r1;
    float* p = g_aggh + (size_t)d * 16;
    {
        float2 f0 = __half22float2(q0[0]), f1 = __half22float2(q0[1]);
        float2 f2 = __half22float2(q0[2]), f3 = __half22float2(q0[3]);
        red4(p + 0, f0.x, f0.y, f1.x, f1.y);
        red4(p + 4, f2.x, f2.y, f3.x, f3.y);
    }
    {
        float2 f0 = __half22float2(q1[0]), f1 = __half22float2(q1[1]);
        float2 f2 = __half22float2(q1[2]), f3 = __half22float2(q1[3]);
        red4(p + 8,  f0.x, f0.y, f1.x, f1.y);
        red4(p + 12, f2.x, f2.y, f3.x, f3.y);
    }
}

// ---------------- kernel 5: h2 = relu(W2^T*aggh + deg*b2); pooled sums -----
__device__ __forceinline__ void flush_graph(int g, const float* acc, float cc) {
    float* ps = g_sums + (size_t)g * 32;
#pragma unroll
    for (int q = 0; q < 8; q++)
        red4(ps + 4*q, acc[4*q], acc[4*q+1], acc[4*q+2], acc[4*q+3]);
    red1(&g_cnt[g], cc);
}

__global__ void __launch_bounds__(256) k_pool(const int* __restrict__ batch,
                       const float* __restrict__ W2, const float* __restrict__ b2) {
    __shared__ float sW[512 + 32];  // W2 (16x32) then b2 (32)
    for (int t = threadIdx.x; t < 544; t += blockDim.x)
        sW[t] = (t < 512) ? W2[t] : b2[t - 512];
    __syncthreads();

    int t = blockIdx.x * blockDim.x + threadIdx.x;
    int base = t * NPT;
    if (base >= N_NODES) return;
    int end = min(base + NPT, N_NODES);

    float acc[32];
    float cc = 0.0f;
    int curg = -1;

#pragma unroll 1
    for (int i = base; i < end; i++) {
        int g = __ldg(&batch[i]);
        float deg = g_deg[i];

        float hv[16];
        const float4* pr = (const float4*)(g_aggh + (size_t)i * 16);
#pragma unroll
        for (int q = 0; q < 4; q++) {
            float4 v = pr[q];
            hv[4*q] = v.x; hv[4*q+1] = v.y; hv[4*q+2] = v.z; hv[4*q+3] = v.w;
        }

        float out[32];
#pragma unroll
        for (int k = 0; k < 32; k++) out[k] = deg * sW[512 + k];
#pragma unroll
        for (int j = 0; j < 16; j++) {
            float hj = hv[j];
            const float4* wrow = (const float4*)(sW + j * 32);
#pragma unroll
            for (int q = 0; q < 8; q++) {
                float4 w = wrow[q];
                out[4*q+0] = fmaf(hj, w.x, out[4*q+0]);
                out[4*q+1] = fmaf(hj, w.y, out[4*q+1]);
                out[4*q+2] = fmaf(hj, w.z, out[4*q+2]);
                out[4*q+3] = fmaf(hj, w.w, out[4*q+3]);
            }
        }
#pragma unroll
        for (int k = 0; k < 32; k++) out[k] = fmaxf(out[k], 0.0f);

        if (g != curg) {
            if (curg >= 0) flush_graph(curg, acc, cc);
#pragma unroll
            for (int k = 0; k < 32; k++) acc[k] = out[k];
            cc = 1.0f;
            curg = g;
        } else {
#pragma unroll
            for (int k = 0; k < 32; k++) acc[k] += out[k];
            cc += 1.0f;
        }
    }
    if (curg >= 0) flush_graph(curg, acc, cc);
}

// ---------------- kernel 6: final MLP over 1024 graphs ---------------------
__global__ void k_final(const float* __restrict__ Wf1, const float* __restrict__ bf1,
                        const float* __restrict__ Wf2, const float* __restrict__ bf2,
                        float* __restrict__ out) {
    int g = blockIdx.x * blockDim.x + threadIdx.x;
    if (g >= N_GRAPHS) return;
    float inv = 1.0f / fmaxf(g_cnt[g], 1.0f);
    float p[32];
#pragma unroll
    for (int k = 0; k < 32; k++) p[k] = g_sums[(size_t)g * 32 + k] * inv;

    float o = __ldg(&bf2[0]);
#pragma unroll
    for (int j = 0; j < 16; j++) {
        float s = __ldg(&bf1[j]);
#pragma unroll
        for (int k = 0; k < 32; k++)
            s = fmaf(p[k], __ldg(&Wf1[k * 16 + j]), s);
        o = fmaf(fmaxf(s, 0.0f), __ldg(&Wf2[j]), o);
    }
    out[g] = o;
}

// ---------------- launch ---------------------------------------------------
extern "C" void kernel_launch(void* const* d_in, const int* in_sizes, int n_in,
                              void* d_out, int out_size) {
    const float2* x     = (const float2*)d_in[0];
    const int*    ei    = (const int*)   d_in[1];
    const int*    batch = (const int*)   d_in[2];
    const float*  W1    = (const float*) d_in[3];
    const float*  b1    = (const float*) d_in[4];
    const float*  W2    = (const float*) d_in[5];
    const float*  b2    = (const float*) d_in[6];
    const float*  Wf1   = (const float*) d_in[7];
    const float*  bf1   = (const float*) d_in[8];
    const float*  Wf2   = (const float*) d_in[9];
    const float*  bf2   = (const float*) d_in[10];
    float* out = (float*)d_out;

    const int TB = 256;
    k_init <<<(N_NODES + TB - 1) / TB, TB>>>(x);
    k_edge1<<<(N_EDGES + TB - 1) / TB, TB>>>(x, ei);
    k_node1<<<(N_NODES + TB - 1) / TB, TB>>>(W1, b1);
    k_edge2<<<(N_EDGES + TB - 1) / TB, TB>>>(ei);
    int pool_threads = (N_NODES + NPT - 1) / NPT;
    k_pool <<<(pool_threads + TB - 1) / TB, TB>>>(batch, W2, b2);
    k_final<<<(N_GRAPHS + TB - 1) / TB, TB>>>(Wf1, bf1, Wf2, bf2, out);
}

// round 9
// speedup vs baseline: 1.4850x; 1.2681x over previous
#include <cuda_runtime.h>
#include <cuda_bf16.h>
#include <cuda_fp16.h>

#define N_NODES  500000
#define N_EDGES  2500000
#define N_GRAPHS 1024
#define NPT      4   // nodes per thread in the pool kernel

// ---------------- scratch (device globals: no allocation allowed) ----------
__device__ __align__(16) float   g_aggx[(size_t)N_NODES * 4];   // {sum_x, sum_y, deg, pad}
__device__ __align__(16) __half2 g_h1h[(size_t)N_NODES * 8];    // relu(conv1) fp16 (16 feats)
__device__ __align__(16) __half2 g_aggh[(size_t)N_NODES * 8];   // fp16 aggregation of h1
__device__ float g_deg[N_NODES];                                // compact degree
__device__ __align__(16) float g_sums[(size_t)N_GRAPHS * 32];   // per-graph feature sums
__device__ float g_cnt[N_GRAPHS];                               // per-graph node counts

// ---------------- vectorized global reductions -----------------------------
__device__ __forceinline__ void red4f(float* p, float a, float b, float c, float d) {
    asm volatile("red.global.add.v4.f32 [%0], {%1, %2, %3, %4};"
                 :: "l"(p), "f"(a), "f"(b), "f"(c), "f"(d) : "memory");
}
__device__ __forceinline__ void red1f(float* p, float a) {
    asm volatile("red.global.add.f32 [%0], %1;" :: "l"(p), "f"(a) : "memory");
}
__device__ __forceinline__ void red4h2(__half2* p, unsigned r0, unsigned r1,
                                       unsigned r2, unsigned r3) {
    asm volatile("red.global.add.noftz.v4.f16x2 [%0], {%1, %2, %3, %4};"
                 :: "l"(p), "r"(r0), "r"(r1), "r"(r2), "r"(r3) : "memory");
}

// ---------------- kernel 1: init self-loop contributions + zero pool bufs --
__global__ void k_init(const float2* __restrict__ x) {
    int i = blockIdx.x * blockDim.x + threadIdx.x;
    if (i < N_GRAPHS) {
        g_cnt[i] = 0.0f;
        float4* s = (float4*)(g_sums + (size_t)i * 32);
#pragma unroll
        for (int q = 0; q < 8; q++) s[q] = make_float4(0.f, 0.f, 0.f, 0.f);
    }
    if (i >= N_NODES) return;
    float2 xi = __ldg(&x[i]);
    ((float4*)g_aggx)[i] = make_float4(xi.x, xi.y, 1.0f, 0.0f);  // self loop, deg=1
}

// ---------------- kernel 2: layer-1 edge scatter (pre-linear) --------------
__global__ void k_edge1(const float2* __restrict__ x, const int* __restrict__ ei) {
    int e = blockIdx.x * blockDim.x + threadIdx.x;
    if (e >= N_EDGES) return;
    int s = __ldg(&ei[e]);
    int d = __ldg(&ei[N_EDGES + e]);
    float2 xs = __ldg(&x[s]);
    red4f(g_aggx + (size_t)d * 4, xs.x, xs.y, 1.0f, 0.0f);
}

// ---------------- kernel 3: h1 = relu(W1^T*aggx + deg*b1) -> f16 x2 bufs ---
__global__ void k_node1(const float* __restrict__ W1, const float* __restrict__ b1) {
    __shared__ float sW[48];   // W1 (2x16) then b1 (16)
    if (threadIdx.x < 32)      sW[threadIdx.x] = W1[threadIdx.x];
    else if (threadIdx.x < 48) sW[threadIdx.x] = b1[threadIdx.x - 32];
    __syncthreads();
    int i = blockIdx.x * blockDim.x + threadIdx.x;
    if (i >= N_NODES) return;
    float4 a = ((const float4*)g_aggx)[i];
    float h[16];
#pragma unroll
    for (int j = 0; j < 16; j++)
        h[j] = fmaxf(fmaf(a.x, sW[j], fmaf(a.y, sW[16 + j], a.z * sW[32 + j])), 0.0f);

    __half2 hp[8];
#pragma unroll
    for (int q = 0; q < 8; q++) hp[q] = __floats2half2_rn(h[2*q], h[2*q+1]);
    float4 v0 = ((float4*)hp)[0];
    float4 v1 = ((float4*)hp)[1];

    float4* ph = (float4*)(g_h1h  + (size_t)i * 8);   // pure copy for edge gather
    float4* pa = (float4*)(g_aggh + (size_t)i * 8);   // self-loop seed (atomics add here)
    ph[0] = v0; ph[1] = v1;
    pa[0] = v0; pa[1] = v1;

    g_deg[i] = a.z;   // compact degree for the pool kernel
}

// ---------------- kernel 4: layer-2 edge scatter (f16 gather + f16 atomics)
__global__ void k_edge2(const int* __restrict__ ei) {
    int e = blockIdx.x * blockDim.x + threadIdx.x;
    if (e >= N_EDGES) return;
    int s = __ldg(&ei[e]);
    int d = __ldg(&ei[N_EDGES + e]);
    const uint4* hp = (const uint4*)(g_h1h + (size_t)s * 8);
    uint4 r0 = __ldg(hp + 0);
    uint4 r1 = __ldg(hp + 1);
    __half2* p = g_aggh + (size_t)d * 8;
    red4h2(p + 0, r0.x, r0.y, r0.z, r0.w);
    red4h2(p + 4, r1.x, r1.y, r1.z, r1.w);
}

// ---------------- kernel 5: h2 = relu(W2^T*aggh + deg*b2); pooled sums -----
__device__ __forceinline__ void flush_graph(int g, const float* acc, float cc) {
    float* ps = g_sums + (size_t)g * 32;
#pragma unroll
    for (int q = 0; q < 8; q++)
        red4f(ps + 4*q, acc[4*q], acc[4*q+1], acc[4*q+2], acc[4*q+3]);
    red1f(&g_cnt[g], cc);
}

__global__ void __launch_bounds__(256) k_pool(const int* __restrict__ batch,
                       const float* __restrict__ W2, const float* __restrict__ b2) {
    __shared__ float sW[512 + 32];  // W2 (16x32) then b2 (32)
    for (int t = threadIdx.x; t < 544; t += blockDim.x)
        sW[t] = (t < 512) ? W2[t] : b2[t - 512];
    __syncthreads();

    int t = blockIdx.x * blockDim.x + threadIdx.x;
    int base = t * NPT;
    if (base >= N_NODES) return;
    int end = min(base + NPT, N_NODES);

    float acc[32];
    float cc = 0.0f;
    int curg = -1;

#pragma unroll 1
    for (int i = base; i < end; i++) {
        int g = __ldg(&batch[i]);
        float deg = g_deg[i];

        const float4* pr = (const float4*)(g_aggh + (size_t)i * 8);
        float4 v0 = pr[0];
        float4 v1 = pr[1];
        const __half2* q0 = (const __half2*)&v0;
        const __half2* q1 = (const __half2*)&v1;
        float hv[16];
#pragma unroll
        for (int q = 0; q < 4; q++) {
            float2 f0 = __half22float2(q0[q]);
            float2 f1 = __half22float2(q1[q]);
            hv[2*q]     = f0.x; hv[2*q+1]     = f0.y;
            hv[8+2*q]   = f1.x; hv[8+2*q+1]   = f1.y;
        }

        float out[32];
#pragma unroll
        for (int k = 0; k < 32; k++) out[k] = deg * sW[512 + k];
#pragma unroll
        for (int j = 0; j < 16; j++) {
            float hj = hv[j];
            const float4* wrow = (const float4*)(sW + j * 32);
#pragma unroll
            for (int q = 0; q < 8; q++) {
                float4 w = wrow[q];
                out[4*q+0] = fmaf(hj, w.x, out[4*q+0]);
                out[4*q+1] = fmaf(hj, w.y, out[4*q+1]);
                out[4*q+2] = fmaf(hj, w.z, out[4*q+2]);
                out[4*q+3] = fmaf(hj, w.w, out[4*q+3]);
            }
        }
#pragma unroll
        for (int k = 0; k < 32; k++) out[k] = fmaxf(out[k], 0.0f);

        if (g != curg) {
            if (curg >= 0) flush_graph(curg, acc, cc);
#pragma unroll
            for (int k = 0; k < 32; k++) acc[k] = out[k];
            cc = 1.0f;
            curg = g;
        } else {
#pragma unroll
            for (int k = 0; k < 32; k++) acc[k] += out[k];
            cc += 1.0f;
        }
    }
    if (curg >= 0) flush_graph(curg, acc, cc);
}

// ---------------- kernel 6: final MLP over 1024 graphs ---------------------
__global__ void k_final(const float* __restrict__ Wf1, const float* __restrict__ bf1,
                        const float* __restrict__ Wf2, const float* __restrict__ bf2,
                        float* __restrict__ out) {
    int g = blockIdx.x * blockDim.x + threadIdx.x;
    if (g >= N_GRAPHS) return;
    float inv = 1.0f / fmaxf(g_cnt[g], 1.0f);
    float p[32];
#pragma unroll
    for (int k = 0; k < 32; k++) p[k] = g_sums[(size_t)g * 32 + k] * inv;

    float o = __ldg(&bf2[0]);
#pragma unroll
    for (int j = 0; j < 16; j++) {
        float s = __ldg(&bf1[j]);
#pragma unroll
        for (int k = 0; k < 32; k++)
            s = fmaf(p[k], __ldg(&Wf1[k * 16 + j]), s);
        o = fmaf(fmaxf(s, 0.0f), __ldg(&Wf2[j]), o);
    }
    out[g] = o;
}

// ---------------- launch ---------------------------------------------------
extern "C" void kernel_launch(void* const* d_in, const int* in_sizes, int n_in,
                              void* d_out, int out_size) {
    const float2* x     = (const float2*)d_in[0];
    const int*    ei    = (const int*)   d_in[1];
    const int*    batch = (const int*)   d_in[2];
    const float*  W1    = (const float*) d_in[3];
    const float*  b1    = (const float*) d_in[4];
    const float*  W2    = (const float*) d_in[5];
    const float*  b2    = (const float*) d_in[6];
    const float*  Wf1   = (const float*) d_in[7];
    const float*  bf1   = (const float*) d_in[8];
    const float*  Wf2   = (const float*) d_in[9];
    const float*  bf2   = (const float*) d_in[10];
    float* out = (float*)d_out;

    const int TB = 256;
    k_init <<<(N_NODES + TB - 1) / TB, TB>>>(x);
    k_edge1<<<(N_EDGES + TB - 1) / TB, TB>>>(x, ei);
    k_node1<<<(N_NODES + TB - 1) / TB, TB>>>(W1, b1);
    k_edge2<<<(N_EDGES + TB - 1) / TB, TB>>>(ei);
    int pool_threads = (N_NODES + NPT - 1) / NPT;
    k_pool <<<(pool_threads + TB - 1) / TB, TB>>>(batch, W2, b2);
    k_final<<<(N_GRAPHS + TB - 1) / TB, TB>>>(Wf1, bf1, Wf2, bf2, out);
}